// round 6
// baseline (speedup 1.0000x reference)
#include <cuda_runtime.h>

// SparseEmbedding: one_hot [B,S,V] fp32 with exactly one nonzero per (b,s) row,
// weight [V,D] fp32, out [B,S,D] fp32.
// Collapse the dense matmul into: scan one_hot for the nonzero (idx,val) per row,
// then out[row] = val * weight[idx].
//
// B=4, S=256, V=50257, D=768 -> BS=1024 rows, total one_hot elems = 51,463,168
// (divisible by 4 -> clean linear float4 scan; per-row stride V is odd so we scan
// the flat array and compute row/col only on a hit).

#define BS_ROWS 1024
#define V_DIM   50257
#define D_DIM   768
#define D4      (D_DIM / 4)

// Scratch (allocation-free rule: __device__ globals). Fully rewritten every
// launch (exactly one nonzero per row), so graph replays are deterministic.
__device__ int   g_idx[BS_ROWS];
__device__ float g_val[BS_ROWS];

__device__ __forceinline__ void record_hit(float4 v, long i4)
{
    float vals[4] = {v.x, v.y, v.z, v.w};
    long base = i4 * 4;
    #pragma unroll
    for (int k = 0; k < 4; k++) {
        if (vals[k] != 0.0f) {
            long e   = base + k;
            int  row = (int)(e / V_DIM);            // rare: div only on hit
            int  col = (int)(e - (long)row * V_DIM);
            g_idx[row] = col;
            g_val[row] = vals[k];
        }
    }
}

__device__ __forceinline__ bool nz(float4 v)
{
    return v.x != 0.0f || v.y != 0.0f || v.z != 0.0f || v.w != 0.0f;
}

__global__ void __launch_bounds__(256)
scan_onehot_kernel(const float4* __restrict__ oh, long n4)
{
    const long stride = (long)gridDim.x * blockDim.x;   // elems per unroll step
    long i = (long)blockIdx.x * blockDim.x + threadIdx.x;

    // Main loop: 4 independent loads in flight per iteration (MLP >= 4/lane).
    for (; i + 3 * stride < n4; i += 4 * stride) {
        float4 v0 = oh[i];
        float4 v1 = oh[i + stride];
        float4 v2 = oh[i + 2 * stride];
        float4 v3 = oh[i + 3 * stride];
        if (nz(v0)) record_hit(v0, i);
        if (nz(v1)) record_hit(v1, i + stride);
        if (nz(v2)) record_hit(v2, i + 2 * stride);
        if (nz(v3)) record_hit(v3, i + 3 * stride);
    }
    // Remainder.
    for (; i < n4; i += stride) {
        float4 v = oh[i];
        if (nz(v)) record_hit(v, i);
    }
}

// 2 rows per block: blockDim = (192, 2). 192 float4 lanes cover D=768.
__global__ void __launch_bounds__(384)
gather_kernel(const float4* __restrict__ w, float4* __restrict__ out)
{
    int   row = blockIdx.x * 2 + threadIdx.y;   // 0..1023
    int   idx = g_idx[row];
    float val = g_val[row];
    float4 v = w[(long)idx * D4 + threadIdx.x];
    out[(long)row * D4 + threadIdx.x] =
        make_float4(v.x * val, v.y * val, v.z * val, v.w * val);
}

extern "C" void kernel_launch(void* const* d_in, const int* in_sizes, int n_in,
                              void* d_out, int out_size)
{
    const float4* one_hot = (const float4*)d_in[0];   // [B,S,V] fp32, flat
    const float4* weight  = (const float4*)d_in[1];   // [V,D] fp32
    float4*       out     = (float4*)d_out;           // [B,S,D] fp32

    // Scan bound from the harness (51,463,168 elems / 4 = 12,865,792 float4).
    const long n4 = (long)in_sizes[0] / 4;

    // 1184 CTAs = 8 waves of 148 SMs; 256 thr; x4 unroll -> ~10 iters/thread.
    scan_onehot_kernel<<<1184, 256>>>(one_hot, n4);

    // 512 blocks x (192,2): each block writes two 768-float output rows.
    gather_kernel<<<BS_ROWS / 2, dim3(192, 2)>>>(weight, out);
}

// round 9
// speedup vs baseline: 1.0715x; 1.0715x over previous
#include <cuda_runtime.h>

// SparseEmbedding: one_hot [B,S,V] fp32, exactly one nonzero per (b,s) row.
// Collapsed to: scan for the (col,val) per row, then out[row] = val * weight[col].
// B=4,S=256,V=50257,D=768. R6: scan unroll x8 + int nonzero test; gather 4 rows/block.

#define BS_ROWS 1024
#define V_DIM   50257
#define D_DIM   768
#define D4      (D_DIM / 4)

__device__ int   g_idx[BS_ROWS];
__device__ float g_val[BS_ROWS];

__device__ __forceinline__ bool nzu(uint4 v)
{
    return (v.x | v.y | v.z | v.w) != 0u;   // zeros are +0.0 = all-zero bits
}

__device__ __forceinline__ void record_hit(uint4 v, long i4)
{
    unsigned bits[4] = {v.x, v.y, v.z, v.w};
    long base = i4 * 4;
    #pragma unroll
    for (int k = 0; k < 4; k++) {
        if (bits[k] != 0u) {
            long e   = base + k;
            int  row = (int)(e / V_DIM);            // rare: only on the 1024 hits
            int  col = (int)(e - (long)row * V_DIM);
            g_idx[row] = col;
            g_val[row] = __uint_as_float(bits[k]);
        }
    }
}

__global__ void __launch_bounds__(256)
scan_onehot_kernel(const uint4* __restrict__ oh, long n4)
{
    const long stride = (long)gridDim.x * blockDim.x;
    long i = (long)blockIdx.x * blockDim.x + threadIdx.x;

    // 8 independent 16B loads in flight per lane.
    for (; i + 7 * stride < n4; i += 8 * stride) {
        uint4 v[8];
        #pragma unroll
        for (int k = 0; k < 8; k++) v[k] = oh[i + k * stride];
        #pragma unroll
        for (int k = 0; k < 8; k++)
            if (nzu(v[k])) record_hit(v[k], i + k * stride);
    }
    for (; i < n4; i += stride) {
        uint4 v = oh[i];
        if (nzu(v)) record_hit(v, i);
    }
}

// 4 rows per block, 192 threads: each thread carries 4 independent
// idx->weight load chains (MLP=4) before any store.
__global__ void __launch_bounds__(192)
gather_kernel(const float4* __restrict__ w, float4* __restrict__ out)
{
    int r0 = blockIdx.x * 4;
    int t  = threadIdx.x;

    int   idx[4];
    float val[4];
    #pragma unroll
    for (int j = 0; j < 4; j++) { idx[j] = g_idx[r0 + j]; val[j] = g_val[r0 + j]; }

    float4 v[4];
    #pragma unroll
    for (int j = 0; j < 4; j++) v[j] = w[(long)idx[j] * D4 + t];

    #pragma unroll
    for (int j = 0; j < 4; j++)
        out[(long)(r0 + j) * D4 + t] =
            make_float4(v[j].x * val[j], v[j].y * val[j],
                        v[j].z * val[j], v[j].w * val[j]);
}

extern "C" void kernel_launch(void* const* d_in, const int* in_sizes, int n_in,
                              void* d_out, int out_size)
{
    const uint4*  one_hot = (const uint4*)d_in[0];    // [B,S,V] fp32, flat
    const float4* weight  = (const float4*)d_in[1];   // [V,D] fp32
    float4*       out     = (float4*)d_out;           // [B,S,D] fp32

    const long n4 = (long)in_sizes[0] / 4;            // 12,865,792 uint4

    // 1184 CTAs = 8 CTAs/SM x 148 SMs; ~42 uint4/thread, ~5 unrolled iters.
    scan_onehot_kernel<<<1184, 256>>>(one_hot, n4);

    // 256 blocks x 192 threads, 4 rows each.
    gather_kernel<<<BS_ROWS / 4, 192>>>(weight, out);
}